// round 13
// baseline (speedup 1.0000x reference)
#include <cuda_runtime.h>
#include <cuda_bf16.h>
#include <cstdint>

#define NN 100000
#define NE 1600000
using u64 = unsigned long long;

#if !defined(__CUDA_ARCH__) || defined(__CUDA_ARCH_FEAT_SM103_ALL)
#define TC_PATH 1
#else
#define TC_PATH 0
#endif

// scratch (static device globals: allocation-free)
__device__ float g_agg[NN * 64];
__device__ float g_Xsr[NN * 128];   // [Xs(64) | Xr+be1(64)] per node

__device__ __forceinline__ void red_add_v4(float* a, float x, float y, float z, float w) {
    asm volatile("red.global.add.v4.f32 [%0], {%1, %2, %3, %4};"
                 :: "l"(a), "f"(x), "f"(y), "f"(z), "f"(w) : "memory");
}
__device__ __forceinline__ void prefetch_l1(const void* p) {
    asm volatile("prefetch.global.L1 [%0];" :: "l"(p));
}

#if TC_PATH
// ===================== tcgen05 machinery (sm_103a only) =====================
__device__ __forceinline__ uint32_t smem_u32(const void* p) {
    return (uint32_t)__cvta_generic_to_shared(p);
}
__device__ __forceinline__ bool elect1() {
    uint32_t pr;
    asm volatile("{\n\t.reg .pred p;\n\telect.sync _|p, 0xFFFFFFFF;\n\tselp.b32 %0, 1, 0, p;\n\t}" : "=r"(pr));
    return pr != 0;
}
#define TC_ALLOC(a, n)  asm volatile("tcgen05.alloc.cta_group::1.sync.aligned.shared::cta.b32 [%0], %1;" :: "r"(a), "r"((uint32_t)(n)) : "memory")
#define TC_RELINQ()     asm volatile("tcgen05.relinquish_alloc_permit.cta_group::1.sync.aligned;")
#define TC_DEALLOC(t, n) asm volatile("tcgen05.dealloc.cta_group::1.sync.aligned.b32 %0, %1;" :: "r"(t), "r"((uint32_t)(n)))
#define TC_COMMIT(mb)   asm volatile("tcgen05.commit.cta_group::1.mbarrier::arrive::one.shared::cluster.b64 [%0];" :: "r"(mb) : "memory")
#define TC_FA()         asm volatile("tcgen05.fence::after_thread_sync;" ::: "memory")
#define TC_FB()         asm volatile("tcgen05.fence::before_thread_sync;" ::: "memory")
#define TC_WLD()        asm volatile("tcgen05.wait::ld.sync.aligned;" ::: "memory")
#define TC_WST()        asm volatile("tcgen05.wait::st.sync.aligned;" ::: "memory")
#define MB_INIT(mb, c)  asm volatile("mbarrier.init.shared.b64 [%0], %1;" :: "r"(mb), "r"((uint32_t)(c)) : "memory")
#define MB_WAIT(mb, ph) do { \
    uint32_t _m = (mb), _p = (ph), _d; \
    asm volatile("{\n\t.reg .pred p;\n\tmbarrier.try_wait.parity.acquire.cta.shared::cta.b64 p, [%1], %2;\n\tselp.b32 %0, 1, 0, p;\n\t}" \
        : "=r"(_d) : "r"(_m), "r"(_p) : "memory"); \
    if (!_d) { \
        asm volatile("{\n\t.reg .pred P1;\n\tWL_%=:\n\tmbarrier.try_wait.parity.acquire.cta.shared::cta.b64 P1, [%0], %1, 0x989680;\n\t@P1 bra.uni WD_%=;\n\tbra.uni WL_%=;\n\tWD_%=:\n\t}" \
            :: "r"(_m), "r"(_p) : "memory"); } \
} while (0)
#define TC_LD_X32(r, tm) \
    asm volatile("tcgen05.ld.sync.aligned.32x32b.x32.b32 " \
        "{%0,%1,%2,%3,%4,%5,%6,%7,%8,%9,%10,%11,%12,%13,%14,%15," \
        "%16,%17,%18,%19,%20,%21,%22,%23,%24,%25,%26,%27,%28,%29,%30,%31}, [%32];" \
        : "=r"((r)[0]),"=r"((r)[1]),"=r"((r)[2]),"=r"((r)[3]),"=r"((r)[4]),"=r"((r)[5]),"=r"((r)[6]),"=r"((r)[7]), \
          "=r"((r)[8]),"=r"((r)[9]),"=r"((r)[10]),"=r"((r)[11]),"=r"((r)[12]),"=r"((r)[13]),"=r"((r)[14]),"=r"((r)[15]), \
          "=r"((r)[16]),"=r"((r)[17]),"=r"((r)[18]),"=r"((r)[19]),"=r"((r)[20]),"=r"((r)[21]),"=r"((r)[22]),"=r"((r)[23]), \
          "=r"((r)[24]),"=r"((r)[25]),"=r"((r)[26]),"=r"((r)[27]),"=r"((r)[28]),"=r"((r)[29]),"=r"((r)[30]),"=r"((r)[31]) \
        : "r"(tm))
#define TC_ST_X32(tm, r) \
    asm volatile("tcgen05.st.sync.aligned.32x32b.x32.b32 [%0], " \
        "{%1,%2,%3,%4,%5,%6,%7,%8,%9,%10,%11,%12,%13,%14,%15,%16," \
        "%17,%18,%19,%20,%21,%22,%23,%24,%25,%26,%27,%28,%29,%30,%31,%32};" \
        :: "r"(tm), \
           "r"((r)[0]),"r"((r)[1]),"r"((r)[2]),"r"((r)[3]),"r"((r)[4]),"r"((r)[5]),"r"((r)[6]),"r"((r)[7]), \
           "r"((r)[8]),"r"((r)[9]),"r"((r)[10]),"r"((r)[11]),"r"((r)[12]),"r"((r)[13]),"r"((r)[14]),"r"((r)[15]), \
           "r"((r)[16]),"r"((r)[17]),"r"((r)[18]),"r"((r)[19]),"r"((r)[20]),"r"((r)[21]),"r"((r)[22]),"r"((r)[23]), \
           "r"((r)[24]),"r"((r)[25]),"r"((r)[26]),"r"((r)[27]),"r"((r)[28]),"r"((r)[29]),"r"((r)[30]),"r"((r)[31]) \
        : "memory")
#define TC_ST_X16(tm, r) \
    asm volatile("tcgen05.st.sync.aligned.32x32b.x16.b32 [%0], " \
        "{%1,%2,%3,%4,%5,%6,%7,%8,%9,%10,%11,%12,%13,%14,%15,%16};" \
        :: "r"(tm), \
           "r"((r)[0]),"r"((r)[1]),"r"((r)[2]),"r"((r)[3]),"r"((r)[4]),"r"((r)[5]),"r"((r)[6]),"r"((r)[7]), \
           "r"((r)[8]),"r"((r)[9]),"r"((r)[10]),"r"((r)[11]),"r"((r)[12]),"r"((r)[13]),"r"((r)[14]),"r"((r)[15]) \
        : "memory")

#define SWZ(b) ((b) ^ (((b) >> 3) & 0x70))
// B (weights in smem, 64 N-rows, K-major, SW128 blocked atoms): n row, k element
#define OFFB(n, k) ((uint32_t)(((uint32_t)((k) >> 6) * 8u + ((uint32_t)(n) >> 3)) * 1024u + SWZ((uint32_t)((((n) & 7) * 128) + ((k) & 63) * 2))))

static __device__ __forceinline__ u64 mkdesc(uint32_t a) {
    return (2ULL << 61) | (1ULL << 46) | (64ULL << 32) | (1ULL << 16) | ((u64)(a >> 4) & 0x3FFF);
}
#define IDESC 0x8100490u  // f32 accum, bf16 x bf16, K-major, M=128, N=64
__device__ __forceinline__ void mma_ts(uint32_t d, uint32_t a, u64 bd, uint32_t en) {
    asm volatile("{\n\t.reg .pred p;\n\tsetp.ne.u32 p, %5, 0;\n\t"
                 "tcgen05.mma.cta_group::1.kind::f16 [%0], [%1], %2, %3, {%4, %4, %4, %4}, p;\n\t}"
                 :: "r"(d), "r"(a), "l"(bd), "r"(IDESC), "r"(0u), "r"(en) : "memory");
}
// 3-pass split-bf16: D = Ah*Bh + Al*Bh + Ah*Bl  (nks K=16 steps per pass)
__device__ __forceinline__ void mma_layer_ts(uint32_t d, uint32_t ahi, uint32_t alo,
                                             u64 bh, u64 bl, int nks, uint32_t en0) {
#pragma unroll
    for (int p = 0; p < 3; p++) {
        uint32_t A = (p == 1) ? alo : ahi;
        u64 B = (p == 2) ? bl : bh;
        for (int ks = 0; ks < nks; ks++)
            mma_ts(d, A + ks * 8, B + (ks >> 2) * 512 + (ks & 3) * 2,
                   (p | ks) ? 1u : en0);
    }
}
__device__ __forceinline__ void split2(float a, float b, uint32_t& hi, uint32_t& lo) {
    __nv_bfloat162 h = __floats2bfloat162_rn(a, b);
    float2 hf = __bfloat1622float2(h);
    __nv_bfloat162 l = __floats2bfloat162_rn(a - hf.x, b - hf.y);
    hi = *(uint32_t*)&h;
    lo = *(uint32_t*)&l;
}
__device__ __forceinline__ void store_wsplit(char* smc, int oh, int ol, uint32_t off, float v) {
    __nv_bfloat16 h = __float2bfloat16(v);
    __nv_bfloat16 l = __float2bfloat16(v - __bfloat162float(h));
    *(unsigned short*)(smc + oh + off) = __bfloat16_as_ushort(h);
    *(unsigned short*)(smc + ol + off) = __bfloat16_as_ushort(l);
}
// load a fp32 row of 64 (16 float4) and split-store into TMEM cols [0,32) hi/lo
__device__ __forceinline__ void stage_row64(const float4* src, uint32_t tm_hi, uint32_t tm_lo) {
    float4 v[16];
#pragma unroll
    for (int j = 0; j < 16; j++) v[j] = src[j];
    uint32_t hi[32], lo[32];
#pragma unroll
    for (int j = 0; j < 16; j++) {
        split2(v[j].x, v[j].y, hi[2 * j], lo[2 * j]);
        split2(v[j].z, v[j].w, hi[2 * j + 1], lo[2 * j + 1]);
    }
    TC_ST_X32(tm_hi, hi);
    TC_ST_X32(tm_lo, lo);
}
#endif  // TC_PATH

// ===================== pre kernel: Xsr = [x@We1_s | x@We1_r + be1]; also zeroes g_agg =====================
#define P_TP 0
#define P_MB 16
#define P_B1 64
#define P_WSH 1024
#define P_WSL 9216
#define P_WRH 17408
#define P_WRL 25600
#define P_SZ  33792
#define P_AHI 0
#define P_ALO 32
#define P_D0  64
#define P_D1  128

__global__ __launch_bounds__(256, 2)
void pre_mma_kernel(const float* __restrict__ x,
                    const float* __restrict__ We1, const float* __restrict__ be1) {
    extern __shared__ char smc[];
    const int tid = threadIdx.x;
#if TC_PATH
    const uint32_t sb = smem_u32(smc);
    const int wid = tid >> 5, lane = tid & 31;
    if (wid == 0) { TC_ALLOC(sb + P_TP, 256); TC_RELINQ(); }
    if (tid == 0) MB_INIT(sb + P_MB, 1);
    float* b1s = (float*)(smc + P_B1);
    if (tid < 64) b1s[tid] = be1[tid];
    for (int i = tid; i < 4096; i += 256) {
        int k = i >> 6, n = i & 63;
        uint32_t o = OFFB(n, k);
        store_wsplit(smc, P_WSH, P_WSL, o, We1[(64 + k) * 64 + n]);
        store_wsplit(smc, P_WRH, P_WRL, o, We1[(128 + k) * 64 + n]);
    }
    __syncthreads();
    uint32_t tmem;
    asm volatile("ld.shared.b32 %0, [%1];" : "=r"(tmem) : "r"(sb + P_TP));
    const u64 dWsh = mkdesc(sb + P_WSH), dWsl = mkdesc(sb + P_WSL);
    const u64 dWrh = mkdesc(sb + P_WRH), dWrl = mkdesc(sb + P_WRL);
    uint32_t ph = 0;
    const int blk = wid & 3;
    const uint32_t rowoff = (uint32_t)blk << 21;
    const int row = blk * 32 + lane;
    const int c0 = (wid >= 4) ? 32 : 0;
    uint32_t d[32];
    const int NT = (NN + 127) / 128;
    const float4* x4 = (const float4*)x;
    float4 zero4 = make_float4(0.f, 0.f, 0.f, 0.f);

    for (int tile = blockIdx.x; tile < NT; tile += gridDim.x) {
        const int base = tile * 128;
        const int n = base + row;
        // zero this tile's g_agg rows (folded zero_agg): each thread zeroes its
        // row's 32-col half (wid<4 -> [0,32), wid>=4 -> [32,64))
        if (n < NN) {
            float4* z = (float4*)&g_agg[(size_t)n * 64 + c0];
#pragma unroll
            for (int j = 0; j < 8; j++) z[j] = zero4;
        }
        {
            float4 v[16];
            if (n < NN) {
#pragma unroll
                for (int j = 0; j < 16; j++) v[j] = x4[(size_t)n * 16 + j];
            } else {
#pragma unroll
                for (int j = 0; j < 16; j++) v[j] = zero4;
            }
            uint32_t hi[32], lo[32];
#pragma unroll
            for (int j = 0; j < 16; j++) {
                split2(v[j].x, v[j].y, hi[2 * j], lo[2 * j]);
                split2(v[j].z, v[j].w, hi[2 * j + 1], lo[2 * j + 1]);
            }
            if (wid < 4) TC_ST_X32(tmem + P_AHI + rowoff, hi);
            else         TC_ST_X32(tmem + P_ALO + rowoff, lo);
        }
        TC_WST(); TC_FB();
        __syncthreads();
        if (wid == 0 && elect1()) {
            TC_FA();
            mma_layer_ts(tmem + P_D0, tmem + P_AHI, tmem + P_ALO, dWsh, dWsl, 4, 0u);
            mma_layer_ts(tmem + P_D1, tmem + P_AHI, tmem + P_ALO, dWrh, dWrl, 4, 0u);
            TC_COMMIT(sb + P_MB);
        }
        MB_WAIT(sb + P_MB, ph); ph ^= 1;
        TC_FA();
        if (n < NN) {
            TC_LD_X32(d, tmem + P_D0 + c0);
            TC_WLD();
#pragma unroll
            for (int j = 0; j < 8; j++)
                *(float4*)&g_Xsr[(size_t)n * 128 + c0 + 4 * j] =
                    make_float4(__uint_as_float(d[4 * j]), __uint_as_float(d[4 * j + 1]),
                                __uint_as_float(d[4 * j + 2]), __uint_as_float(d[4 * j + 3]));
            TC_LD_X32(d, tmem + P_D1 + c0);
            TC_WLD();
#pragma unroll
            for (int j = 0; j < 8; j++)
                *(float4*)&g_Xsr[(size_t)n * 128 + 64 + c0 + 4 * j] =
                    make_float4(__uint_as_float(d[4 * j]) + b1s[c0 + 4 * j],
                                __uint_as_float(d[4 * j + 1]) + b1s[c0 + 4 * j + 1],
                                __uint_as_float(d[4 * j + 2]) + b1s[c0 + 4 * j + 2],
                                __uint_as_float(d[4 * j + 3]) + b1s[c0 + 4 * j + 3]);
        } else {
            TC_LD_X32(d, tmem + P_D0 + c0); TC_WLD();
            TC_LD_X32(d, tmem + P_D1 + c0); TC_WLD();
        }
        TC_FB();
        __syncthreads();
    }
    if (wid == 0) TC_DEALLOC(tmem, 256);
#else
    for (int i = blockIdx.x * blockDim.x + tid; i < NN; i += gridDim.x * blockDim.x)
        for (int j = 0; j < 64; j++) {
            float s = 0.f, r = be1[j];
            for (int k = 0; k < 64; k++) {
                s += x[(size_t)i * 64 + k] * We1[(64 + k) * 64 + j];
                r += x[(size_t)i * 64 + k] * We1[(128 + k) * 64 + j];
            }
            g_Xsr[(size_t)i * 128 + j] = s;
            g_Xsr[(size_t)i * 128 + 64 + j] = r;
            g_agg[(size_t)i * 64 + j] = 0.f;
        }
#endif
}

// ===================== edge kernel: 256 edges/tile, reg indices, split commits, L1 prefetch =====================
#define E_TP  0
#define E_MB0 16
#define E_MB1 24
#define E_B2  64
#define E_B3  320
#define E_W1H 1024
#define E_W1L 9216
#define E_W2H 17408
#define E_W2L 25600
#define E_W3H 33792
#define E_W3L 41984
#define E_SZ  50176
// TMEM (256 cols/CTA): h0: AHI 0 ALO 32 D 64; h1: AHI 128 ALO 160 D 192
#define H_AHI(h) ((h) ? 128u : 0u)
#define H_ALO(h) ((h) ? 160u : 32u)
#define H_D(h)   ((h) ? 192u : 64u)

__global__ __launch_bounds__(256, 2)
void edge_mma_kernel(const float* __restrict__ x,
                     const float* __restrict__ e,
                     const int* __restrict__ senders,
                     const int* __restrict__ receivers,
                     const float* __restrict__ We1, const float* __restrict__ be1,
                     const float* __restrict__ We2, const float* __restrict__ be2,
                     const float* __restrict__ We3, const float* __restrict__ be3) {
    extern __shared__ char smc[];
    const int tid = threadIdx.x;
#if TC_PATH
    const uint32_t sb = smem_u32(smc);
    const int wid = tid >> 5, lane = tid & 31;
    if (wid == 0) { TC_ALLOC(sb + E_TP, 256); TC_RELINQ(); }
    if (tid == 0) { MB_INIT(sb + E_MB0, 1); MB_INIT(sb + E_MB1, 1); }
    float* b2s = (float*)(smc + E_B2);
    float* b3s = (float*)(smc + E_B3);
    if (tid < 64) { b2s[tid] = be2[tid]; b3s[tid] = be3[tid]; }
    for (int i = tid; i < 4096; i += 256) {
        int k = i >> 6, n = i & 63;
        uint32_t o = OFFB(n, k);
        store_wsplit(smc, E_W1H, E_W1L, o, We1[k * 64 + n]);   // e-part rows [0,64)
        store_wsplit(smc, E_W2H, E_W2L, o, We2[i]);
        store_wsplit(smc, E_W3H, E_W3L, o, We3[i]);
    }
    __syncthreads();
    uint32_t tmem;
    asm volatile("ld.shared.b32 %0, [%1];" : "=r"(tmem) : "r"(sb + E_TP));
    const u64 dW1h = mkdesc(sb + E_W1H), dW1l = mkdesc(sb + E_W1L);
    const u64 dW2h = mkdesc(sb + E_W2H), dW2l = mkdesc(sb + E_W2L);
    const u64 dW3h = mkdesc(sb + E_W3H), dW3l = mkdesc(sb + E_W3L);
    const float4* e4 = (const float4*)e;
    uint32_t ph0 = 0, ph1 = 0;
    const int blk = wid & 3;
    const uint32_t rowoff = (uint32_t)blk << 21;
    const int row = blk * 32 + lane;
    const int half = (wid >= 4) ? 1 : 0;
    const int c0 = half ? 32 : 0;
    uint32_t d[32];
    const int NT2 = NE / 256;

    for (int tile = blockIdx.x; tile < NT2; tile += gridDim.x) {
        const int base = tile * 256;
        // per-thread edge indices for both halves (registers, no smem)
        const int s0 = senders[base + row],        t0 = receivers[base + row];
        const int s1 = senders[base + 128 + row],  t1 = receivers[base + 128 + row];
        // L1 prefetch of the gather rows this thread will read in epi1 (zero reg cost)
        prefetch_l1(&g_Xsr[(size_t)s0 * 128 + c0]);
        prefetch_l1(&g_Xsr[(size_t)t0 * 128 + 64 + c0]);
        prefetch_l1(&g_Xsr[(size_t)s1 * 128 + c0]);
        prefetch_l1(&g_Xsr[(size_t)t1 * 128 + 64 + c0]);
        // ---- stage e rows of this warp's half ----
        stage_row64(&e4[(size_t)(base + half * 128 + row) * 16],
                    tmem + H_AHI(half) + rowoff, tmem + H_ALO(half) + rowoff);
        TC_WST(); TC_FB();
        __syncthreads();
        // ---- M1: h0 -> mb0, h1 -> mb1 ----
        if (wid == 0 && elect1()) {
            TC_FA();
            mma_layer_ts(tmem + H_D(0), tmem + H_AHI(0), tmem + H_ALO(0), dW1h, dW1l, 4, 0u);
            TC_COMMIT(sb + E_MB0);
            mma_layer_ts(tmem + H_D(1), tmem + H_AHI(1), tmem + H_ALO(1), dW1h, dW1l, 4, 0u);
            TC_COMMIT(sb + E_MB1);
        }
        // ---- epi1 h0 (overlaps M1 h1 drain) ----
        MB_WAIT(sb + E_MB0, ph0); ph0 ^= 1;
        TC_FA();
        {
            TC_LD_X32(d, tmem + H_D(0) + c0);
            const float4* ps = (const float4*)&g_Xsr[(size_t)s0 * 128 + c0];
            const float4* pt = (const float4*)&g_Xsr[(size_t)t0 * 128 + 64 + c0];
            TC_WLD();
            uint32_t hi[16], lo[16];
#pragma unroll
            for (int j = 0; j < 8; j++) {
                float4 a = ps[j], b = pt[j];
                float v0 = fmaxf(__uint_as_float(d[4 * j])     + a.x + b.x, 0.f);
                float v1 = fmaxf(__uint_as_float(d[4 * j + 1]) + a.y + b.y, 0.f);
                float v2 = fmaxf(__uint_as_float(d[4 * j + 2]) + a.z + b.z, 0.f);
                float v3 = fmaxf(__uint_as_float(d[4 * j + 3]) + a.w + b.w, 0.f);
                split2(v0, v1, hi[2 * j], lo[2 * j]);
                split2(v2, v3, hi[2 * j + 1], lo[2 * j + 1]);
            }
            TC_ST_X16(tmem + H_AHI(0) + (c0 >> 1) + rowoff, hi);
            TC_ST_X16(tmem + H_ALO(0) + (c0 >> 1) + rowoff, lo);
        }
        // ---- epi1 h1 ----
        MB_WAIT(sb + E_MB1, ph1); ph1 ^= 1;
        TC_FA();
        {
            TC_LD_X32(d, tmem + H_D(1) + c0);
            const float4* ps = (const float4*)&g_Xsr[(size_t)s1 * 128 + c0];
            const float4* pt = (const float4*)&g_Xsr[(size_t)t1 * 128 + 64 + c0];
            TC_WLD();
            uint32_t hi[16], lo[16];
#pragma unroll
            for (int j = 0; j < 8; j++) {
                float4 a = ps[j], b = pt[j];
                float v0 = fmaxf(__uint_as_float(d[4 * j])     + a.x + b.x, 0.f);
                float v1 = fmaxf(__uint_as_float(d[4 * j + 1]) + a.y + b.y, 0.f);
                float v2 = fmaxf(__uint_as_float(d[4 * j + 2]) + a.z + b.z, 0.f);
                float v3 = fmaxf(__uint_as_float(d[4 * j + 3]) + a.w + b.w, 0.f);
                split2(v0, v1, hi[2 * j], lo[2 * j]);
                split2(v2, v3, hi[2 * j + 1], lo[2 * j + 1]);
            }
            TC_ST_X16(tmem + H_AHI(1) + (c0 >> 1) + rowoff, hi);
            TC_ST_X16(tmem + H_ALO(1) + (c0 >> 1) + rowoff, lo);
        }
        TC_WST(); TC_FB();
        __syncthreads();
        // ---- M2 ----
        if (wid == 0 && elect1()) {
            TC_FA();
            mma_layer_ts(tmem + H_D(0), tmem + H_AHI(0), tmem + H_ALO(0), dW2h, dW2l, 4, 0u);
            TC_COMMIT(sb + E_MB0);
            mma_layer_ts(tmem + H_D(1), tmem + H_AHI(1), tmem + H_ALO(1), dW2h, dW2l, 4, 0u);
            TC_COMMIT(sb + E_MB1);
        }
        // ---- epi2 h0 / h1 ----
#pragma unroll
        for (int h = 0; h < 2; h++) {
            if (h == 0) { MB_WAIT(sb + E_MB0, ph0); ph0 ^= 1; }
            else        { MB_WAIT(sb + E_MB1, ph1); ph1 ^= 1; }
            TC_FA();
            TC_LD_X32(d, tmem + H_D(h) + c0);
            TC_WLD();
            uint32_t hi[16], lo[16];
#pragma unroll
            for (int j = 0; j < 16; j++) {
                float a = fmaxf(__uint_as_float(d[2 * j])     + b2s[c0 + 2 * j], 0.f);
                float b = fmaxf(__uint_as_float(d[2 * j + 1]) + b2s[c0 + 2 * j + 1], 0.f);
                split2(a, b, hi[j], lo[j]);
            }
            TC_ST_X16(tmem + H_AHI(h) + (c0 >> 1) + rowoff, hi);
            TC_ST_X16(tmem + H_ALO(h) + (c0 >> 1) + rowoff, lo);
        }
        TC_WST(); TC_FB();
        __syncthreads();
        // ---- M3 ----
        if (wid == 0 && elect1()) {
            TC_FA();
            mma_layer_ts(tmem + H_D(0), tmem + H_AHI(0), tmem + H_ALO(0), dW3h, dW3l, 4, 0u);
            TC_COMMIT(sb + E_MB0);
            mma_layer_ts(tmem + H_D(1), tmem + H_AHI(1), tmem + H_ALO(1), dW3h, dW3l, 4, 0u);
            TC_COMMIT(sb + E_MB1);
        }
        // ---- epi3 h0 / h1: segment sum ----
#pragma unroll
        for (int h = 0; h < 2; h++) {
            if (h == 0) { MB_WAIT(sb + E_MB0, ph0); ph0 ^= 1; }
            else        { MB_WAIT(sb + E_MB1, ph1); ph1 ^= 1; }
            TC_FA();
            TC_LD_X32(d, tmem + H_D(h) + c0);
            TC_WLD();
            float* p = &g_agg[(size_t)(h ? t1 : t0) * 64 + c0];
#pragma unroll
            for (int jj = 0; jj < 4; jj++) {
                float v[8];
#pragma unroll
                for (int j = 0; j < 8; j++)
                    v[j] = __uint_as_float(d[jj * 8 + j]) + b3s[c0 + jj * 8 + j];
                red_add_v4(p + jj * 8, v[0], v[1], v[2], v[3]);
                red_add_v4(p + jj * 8 + 4, v[4], v[5], v[6], v[7]);
            }
        }
        TC_FB();
    }
    if (wid == 0) TC_DEALLOC(tmem, 256);
#else
    // naive correct fallback (compiled for non-sm_103a passes only)
    for (int i = blockIdx.x * blockDim.x + tid; i < NE; i += gridDim.x * blockDim.x) {
        int s = senders[i], t = receivers[i];
        float h1[64], h2[64];
        for (int j = 0; j < 64; j++) {
            float a = be1[j];
            for (int k = 0; k < 64; k++) a += e[(size_t)i * 64 + k] * We1[k * 64 + j];
            for (int k = 0; k < 64; k++) a += x[(size_t)s * 64 + k] * We1[(64 + k) * 64 + j];
            for (int k = 0; k < 64; k++) a += x[(size_t)t * 64 + k] * We1[(128 + k) * 64 + j];
            h1[j] = fmaxf(a, 0.f);
        }
        for (int j = 0; j < 64; j++) {
            float a = be2[j];
            for (int k = 0; k < 64; k++) a += h1[k] * We2[k * 64 + j];
            h2[j] = fmaxf(a, 0.f);
        }
        for (int j = 0; j < 64; j++) {
            float a = be3[j];
            for (int k = 0; k < 64; k++) a += h2[k] * We3[k * 64 + j];
            atomicAdd(&g_agg[(size_t)t * 64 + j], a);
        }
    }
#endif
}

// ===================== node kernel =====================
#define N_TP 0
#define N_MB 16
#define N_B1 64
#define N_B2 320
#define N_B3 576
#define N_W1H 1024
#define N_W1L 17408
#define N_W2H 33792
#define N_W2L 41984
#define N_W3H 50176
#define N_W3L 58368
#define N_SZ 66560
#define N_AHI 0
#define N_ALO 64
#define N_D   128

__global__ __launch_bounds__(256, 2)
void node_mma_kernel(const float* __restrict__ x,
                     const float* __restrict__ Wn1, const float* __restrict__ bn1,
                     const float* __restrict__ Wn2, const float* __restrict__ bn2,
                     const float* __restrict__ Wn3, const float* __restrict__ bn3,
                     float* __restrict__ out) {
    extern __shared__ char smc[];
    const int tid = threadIdx.x;
#if TC_PATH
    const uint32_t sb = smem_u32(smc);
    const int wid = tid >> 5, lane = tid & 31;
    if (wid == 0) { TC_ALLOC(sb + N_TP, 256); TC_RELINQ(); }
    if (tid == 0) MB_INIT(sb + N_MB, 1);
    float* b1s = (float*)(smc + N_B1);
    float* b2s = (float*)(smc + N_B2);
    float* b3s = (float*)(smc + N_B3);
    if (tid < 64) { b1s[tid] = bn1[tid]; b2s[tid] = bn2[tid]; b3s[tid] = bn3[tid]; }
    for (int i = tid; i < 8192; i += 256) {
        int k = i >> 6, n = i & 63;
        store_wsplit(smc, N_W1H, N_W1L, OFFB(n, k), Wn1[i]);
    }
    for (int i = tid; i < 4096; i += 256) {
        int k = i >> 6, n = i & 63;
        uint32_t o = OFFB(n, k);
        store_wsplit(smc, N_W2H, N_W2L, o, Wn2[i]);
        store_wsplit(smc, N_W3H, N_W3L, o, Wn3[i]);
    }
    __syncthreads();
    uint32_t tmem;
    asm volatile("ld.shared.b32 %0, [%1];" : "=r"(tmem) : "r"(sb + N_TP));
    const u64 dW1h = mkdesc(sb + N_W1H), dW1l = mkdesc(sb + N_W1L);
    const u64 dW2h = mkdesc(sb + N_W2H), dW2l = mkdesc(sb + N_W2L);
    const u64 dW3h = mkdesc(sb + N_W3H), dW3l = mkdesc(sb + N_W3L);
    const float4* x4 = (const float4*)x;
    const float4* ag4 = (const float4*)g_agg;
    uint32_t ph = 0;
    const int blk = wid & 3;
    const uint32_t rowoff = (uint32_t)blk << 21;
    const int row = blk * 32 + lane;
    const int c0 = (wid >= 4) ? 32 : 0;
    uint32_t d[32];
    const int NT = (NN + 127) / 128;
    float4 zero4 = make_float4(0.f, 0.f, 0.f, 0.f);

    for (int tile = blockIdx.x; tile < NT; tile += gridDim.x) {
        const int base = tile * 128;
        const int n = base + row;
        {
            const float4* src = (wid < 4) ? &x4[(size_t)n * 16] : &ag4[(size_t)n * 16];
            float4 v[16];
            if (n < NN) {
#pragma unroll
                for (int j = 0; j < 16; j++) v[j] = src[j];
            } else {
#pragma unroll
                for (int j = 0; j < 16; j++) v[j] = zero4;
            }
            uint32_t hi[32], lo[32];
#pragma unroll
            for (int j = 0; j < 16; j++) {
                split2(v[j].x, v[j].y, hi[2 * j], lo[2 * j]);
                split2(v[j].z, v[j].w, hi[2 * j + 1], lo[2 * j + 1]);
            }
            uint32_t off = (wid < 4) ? 0u : 32u;
            TC_ST_X32(tmem + N_AHI + off + rowoff, hi);
            TC_ST_X32(tmem + N_ALO + off + rowoff, lo);
        }
        TC_WST(); TC_FB();
        __syncthreads();
        if (wid == 0 && elect1()) {
            TC_FA();
            mma_layer_ts(tmem + N_D, tmem + N_AHI, tmem + N_ALO, dW1h, dW1l, 8, 0u);
            TC_COMMIT(sb + N_MB);
        }
        MB_WAIT(sb + N_MB, ph); ph ^= 1;
        TC_FA();
        TC_LD_X32(d, tmem + N_D + c0);
        TC_WLD();
        {
            uint32_t hi[16], lo[16];
#pragma unroll
            for (int j = 0; j < 16; j++) {
                float a = fmaxf(__uint_as_float(d[2 * j])     + b1s[c0 + 2 * j], 0.f);
                float b = fmaxf(__uint_as_float(d[2 * j + 1]) + b1s[c0 + 2 * j + 1], 0.f);
                split2(a, b, hi[j], lo[j]);
            }
            TC_ST_X16(tmem + N_AHI + (c0 >> 1) + rowoff, hi);
            TC_ST_X16(tmem + N_ALO + (c0 >> 1) + rowoff, lo);
            TC_WST();
        }
        TC_FB();
        __syncthreads();
        if (wid == 0 && elect1()) {
            TC_FA();
            mma_layer_ts(tmem + N_D, tmem + N_AHI, tmem + N_ALO, dW2h, dW2l, 4, 0u);
            TC_COMMIT(sb + N_MB);
        }
        MB_WAIT(sb + N_MB, ph); ph ^= 1;
        TC_FA();
        TC_LD_X32(d, tmem + N_D + c0);
        TC_WLD();
        {
            uint32_t hi[16], lo[16];
#pragma unroll
            for (int j = 0; j < 16; j++) {
                float a = fmaxf(__uint_as_float(d[2 * j])     + b2s[c0 + 2 * j], 0.f);
                float b = fmaxf(__uint_as_float(d[2 * j + 1]) + b2s[c0 + 2 * j + 1], 0.f);
                split2(a, b, hi[j], lo[j]);
            }
            TC_ST_X16(tmem + N_AHI + (c0 >> 1) + rowoff, hi);
            TC_ST_X16(tmem + N_ALO + (c0 >> 1) + rowoff, lo);
            TC_WST();
        }
        TC_FB();
        __syncthreads();
        if (wid == 0 && elect1()) {
            TC_FA();
            mma_layer_ts(tmem + N_D, tmem + N_AHI, tmem + N_ALO, dW3h, dW3l, 4, 0u);
            TC_COMMIT(sb + N_MB);
        }
        MB_WAIT(sb + N_MB, ph); ph ^= 1;
        TC_FA();
        TC_LD_X32(d, tmem + N_D + c0);
        TC_WLD(); TC_FB();
        if (n < NN) {
#pragma unroll
            for (int jj = 0; jj < 4; jj++) {
                float v[8];
#pragma unroll
                for (int j = 0; j < 8; j++)
                    v[j] = __uint_as_float(d[jj * 8 + j]) + b3s[c0 + jj * 8 + j];
                *(float4*)&out[(size_t)n * 64 + c0 + jj * 8]     = make_float4(v[0], v[1], v[2], v[3]);
                *(float4*)&out[(size_t)n * 64 + c0 + jj * 8 + 4] = make_float4(v[4], v[5], v[6], v[7]);
            }
        }
        __syncthreads();
    }
    if (wid == 0) TC_DEALLOC(tmem, 256);
#else
    for (int i = blockIdx.x * blockDim.x + tid; i < NN; i += gridDim.x * blockDim.x) {
        float h1[64], h2[64];
        for (int j = 0; j < 64; j++) {
            float a = bn1[j];
            for (int k = 0; k < 64; k++) a += x[(size_t)i * 64 + k] * Wn1[k * 64 + j];
            for (int k = 0; k < 64; k++) a += g_agg[(size_t)i * 64 + k] * Wn1[(64 + k) * 64 + j];
            h1[j] = fmaxf(a, 0.f);
        }
        for (int j = 0; j < 64; j++) {
            float a = bn2[j];
            for (int k = 0; k < 64; k++) a += h1[k] * Wn2[k * 64 + j];
            h2[j] = fmaxf(a, 0.f);
        }
        for (int j = 0; j < 64; j++) {
            float a = bn3[j];
            for (int k = 0; k < 64; k++) a += h2[k] * Wn3[k * 64 + j];
            out[(size_t)i * 64 + j] = a;
        }
    }
#endif
}

// ===================== launch =====================
extern "C" void kernel_launch(void* const* d_in, const int* in_sizes, int n_in,
                              void* d_out, int out_size) {
    const float* x         = (const float*)d_in[0];
    const float* e         = (const float*)d_in[1];
    const int*   senders   = (const int*)d_in[2];
    const int*   receivers = (const int*)d_in[3];
    const float* We1 = (const float*)d_in[4];
    const float* be1 = (const float*)d_in[5];
    const float* We2 = (const float*)d_in[6];
    const float* be2 = (const float*)d_in[7];
    const float* We3 = (const float*)d_in[8];
    const float* be3 = (const float*)d_in[9];
    const float* Wn1 = (const float*)d_in[10];
    const float* bn1 = (const float*)d_in[11];
    const float* Wn2 = (const float*)d_in[12];
    const float* bn2 = (const float*)d_in[13];
    const float* Wn3 = (const float*)d_in[14];
    const float* bn3 = (const float*)d_in[15];
    float* out = (float*)d_out;

    cudaFuncSetAttribute(pre_mma_kernel,  cudaFuncAttributeMaxDynamicSharedMemorySize, P_SZ);
    cudaFuncSetAttribute(edge_mma_kernel, cudaFuncAttributeMaxDynamicSharedMemorySize, E_SZ);
    cudaFuncSetAttribute(node_mma_kernel, cudaFuncAttributeMaxDynamicSharedMemorySize, N_SZ);

    pre_mma_kernel<<<304, 256, P_SZ>>>(x, We1, be1);
    edge_mma_kernel<<<304, 256, E_SZ>>>(x, e, senders, receivers,
                                        We1, be1, We2, be2, We3, be3);
    node_mma_kernel<<<304, 256, N_SZ>>>(x, Wn1, bn1, Wn2, bn2, Wn3, bn3, out);
}

// round 14
// speedup vs baseline: 1.0175x; 1.0175x over previous
#include <cuda_runtime.h>
#include <cuda_bf16.h>
#include <cstdint>

#define NN 100000
#define NE 1600000
using u64 = unsigned long long;

#if !defined(__CUDA_ARCH__) || defined(__CUDA_ARCH_FEAT_SM103_ALL)
#define TC_PATH 1
#else
#define TC_PATH 0
#endif

// scratch (static device globals: allocation-free)
__device__ float g_agg[NN * 64];
__device__ float g_Xsr[NN * 128];   // [Xs(64) | Xr+be1(64)] per node

__device__ __forceinline__ void red_add_v4(float* a, float x, float y, float z, float w) {
    asm volatile("red.global.add.v4.f32 [%0], {%1, %2, %3, %4};"
                 :: "l"(a), "f"(x), "f"(y), "f"(z), "f"(w) : "memory");
}

#if TC_PATH
// ===================== tcgen05 machinery (sm_103a only) =====================
__device__ __forceinline__ uint32_t smem_u32(const void* p) {
    return (uint32_t)__cvta_generic_to_shared(p);
}
__device__ __forceinline__ bool elect1() {
    uint32_t pr;
    asm volatile("{\n\t.reg .pred p;\n\telect.sync _|p, 0xFFFFFFFF;\n\tselp.b32 %0, 1, 0, p;\n\t}" : "=r"(pr));
    return pr != 0;
}
#define TC_ALLOC(a, n)  asm volatile("tcgen05.alloc.cta_group::1.sync.aligned.shared::cta.b32 [%0], %1;" :: "r"(a), "r"((uint32_t)(n)) : "memory")
#define TC_RELINQ()     asm volatile("tcgen05.relinquish_alloc_permit.cta_group::1.sync.aligned;")
#define TC_DEALLOC(t, n) asm volatile("tcgen05.dealloc.cta_group::1.sync.aligned.b32 %0, %1;" :: "r"(t), "r"((uint32_t)(n)))
#define TC_COMMIT(mb)   asm volatile("tcgen05.commit.cta_group::1.mbarrier::arrive::one.shared::cluster.b64 [%0];" :: "r"(mb) : "memory")
#define TC_FA()         asm volatile("tcgen05.fence::after_thread_sync;" ::: "memory")
#define TC_FB()         asm volatile("tcgen05.fence::before_thread_sync;" ::: "memory")
#define TC_WLD()        asm volatile("tcgen05.wait::ld.sync.aligned;" ::: "memory")
#define TC_WST()        asm volatile("tcgen05.wait::st.sync.aligned;" ::: "memory")
#define MB_INIT(mb, c)  asm volatile("mbarrier.init.shared.b64 [%0], %1;" :: "r"(mb), "r"((uint32_t)(c)) : "memory")
#define MB_WAIT(mb, ph) do { \
    uint32_t _m = (mb), _p = (ph), _d; \
    asm volatile("{\n\t.reg .pred p;\n\tmbarrier.try_wait.parity.acquire.cta.shared::cta.b64 p, [%1], %2;\n\tselp.b32 %0, 1, 0, p;\n\t}" \
        : "=r"(_d) : "r"(_m), "r"(_p) : "memory"); \
    if (!_d) { \
        asm volatile("{\n\t.reg .pred P1;\n\tWL_%=:\n\tmbarrier.try_wait.parity.acquire.cta.shared::cta.b64 P1, [%0], %1, 0x989680;\n\t@P1 bra.uni WD_%=;\n\tbra.uni WL_%=;\n\tWD_%=:\n\t}" \
            :: "r"(_m), "r"(_p) : "memory"); } \
} while (0)
#define TC_LD_X32(r, tm) \
    asm volatile("tcgen05.ld.sync.aligned.32x32b.x32.b32 " \
        "{%0,%1,%2,%3,%4,%5,%6,%7,%8,%9,%10,%11,%12,%13,%14,%15," \
        "%16,%17,%18,%19,%20,%21,%22,%23,%24,%25,%26,%27,%28,%29,%30,%31}, [%32];" \
        : "=r"((r)[0]),"=r"((r)[1]),"=r"((r)[2]),"=r"((r)[3]),"=r"((r)[4]),"=r"((r)[5]),"=r"((r)[6]),"=r"((r)[7]), \
          "=r"((r)[8]),"=r"((r)[9]),"=r"((r)[10]),"=r"((r)[11]),"=r"((r)[12]),"=r"((r)[13]),"=r"((r)[14]),"=r"((r)[15]), \
          "=r"((r)[16]),"=r"((r)[17]),"=r"((r)[18]),"=r"((r)[19]),"=r"((r)[20]),"=r"((r)[21]),"=r"((r)[22]),"=r"((r)[23]), \
          "=r"((r)[24]),"=r"((r)[25]),"=r"((r)[26]),"=r"((r)[27]),"=r"((r)[28]),"=r"((r)[29]),"=r"((r)[30]),"=r"((r)[31]) \
        : "r"(tm))
#define TC_ST_X32(tm, r) \
    asm volatile("tcgen05.st.sync.aligned.32x32b.x32.b32 [%0], " \
        "{%1,%2,%3,%4,%5,%6,%7,%8,%9,%10,%11,%12,%13,%14,%15,%16," \
        "%17,%18,%19,%20,%21,%22,%23,%24,%25,%26,%27,%28,%29,%30,%31,%32};" \
        :: "r"(tm), \
           "r"((r)[0]),"r"((r)[1]),"r"((r)[2]),"r"((r)[3]),"r"((r)[4]),"r"((r)[5]),"r"((r)[6]),"r"((r)[7]), \
           "r"((r)[8]),"r"((r)[9]),"r"((r)[10]),"r"((r)[11]),"r"((r)[12]),"r"((r)[13]),"r"((r)[14]),"r"((r)[15]), \
           "r"((r)[16]),"r"((r)[17]),"r"((r)[18]),"r"((r)[19]),"r"((r)[20]),"r"((r)[21]),"r"((r)[22]),"r"((r)[23]), \
           "r"((r)[24]),"r"((r)[25]),"r"((r)[26]),"r"((r)[27]),"r"((r)[28]),"r"((r)[29]),"r"((r)[30]),"r"((r)[31]) \
        : "memory")
#define TC_ST_X16(tm, r) \
    asm volatile("tcgen05.st.sync.aligned.32x32b.x16.b32 [%0], " \
        "{%1,%2,%3,%4,%5,%6,%7,%8,%9,%10,%11,%12,%13,%14,%15,%16};" \
        :: "r"(tm), \
           "r"((r)[0]),"r"((r)[1]),"r"((r)[2]),"r"((r)[3]),"r"((r)[4]),"r"((r)[5]),"r"((r)[6]),"r"((r)[7]), \
           "r"((r)[8]),"r"((r)[9]),"r"((r)[10]),"r"((r)[11]),"r"((r)[12]),"r"((r)[13]),"r"((r)[14]),"r"((r)[15]) \
        : "memory")

#define SWZ(b) ((b) ^ (((b) >> 3) & 0x70))
// B (weights in smem, 64 N-rows, K-major, SW128 blocked atoms): n row, k element
#define OFFB(n, k) ((uint32_t)(((uint32_t)((k) >> 6) * 8u + ((uint32_t)(n) >> 3)) * 1024u + SWZ((uint32_t)((((n) & 7) * 128) + ((k) & 63) * 2))))

static __device__ __forceinline__ u64 mkdesc(uint32_t a) {
    return (2ULL << 61) | (1ULL << 46) | (64ULL << 32) | (1ULL << 16) | ((u64)(a >> 4) & 0x3FFF);
}
#define IDESC 0x8100490u  // f32 accum, bf16 x bf16, K-major, M=128, N=64
__device__ __forceinline__ void mma_ts(uint32_t d, uint32_t a, u64 bd, uint32_t en) {
    asm volatile("{\n\t.reg .pred p;\n\tsetp.ne.u32 p, %5, 0;\n\t"
                 "tcgen05.mma.cta_group::1.kind::f16 [%0], [%1], %2, %3, {%4, %4, %4, %4}, p;\n\t}"
                 :: "r"(d), "r"(a), "l"(bd), "r"(IDESC), "r"(0u), "r"(en) : "memory");
}
// 3-pass split-bf16: D = Ah*Bh + Al*Bh + Ah*Bl  (nks K=16 steps per pass)
__device__ __forceinline__ void mma_layer_ts(uint32_t d, uint32_t ahi, uint32_t alo,
                                             u64 bh, u64 bl, int nks, uint32_t en0) {
#pragma unroll
    for (int p = 0; p < 3; p++) {
        uint32_t A = (p == 1) ? alo : ahi;
        u64 B = (p == 2) ? bl : bh;
        for (int ks = 0; ks < nks; ks++)
            mma_ts(d, A + ks * 8, B + (ks >> 2) * 512 + (ks & 3) * 2,
                   (p | ks) ? 1u : en0);
    }
}
__device__ __forceinline__ void split2(float a, float b, uint32_t& hi, uint32_t& lo) {
    __nv_bfloat162 h = __floats2bfloat162_rn(a, b);
    float2 hf = __bfloat1622float2(h);
    __nv_bfloat162 l = __floats2bfloat162_rn(a - hf.x, b - hf.y);
    hi = *(uint32_t*)&h;
    lo = *(uint32_t*)&l;
}
__device__ __forceinline__ void store_wsplit(char* smc, int oh, int ol, uint32_t off, float v) {
    __nv_bfloat16 h = __float2bfloat16(v);
    __nv_bfloat16 l = __float2bfloat16(v - __bfloat162float(h));
    *(unsigned short*)(smc + oh + off) = __bfloat16_as_ushort(h);
    *(unsigned short*)(smc + ol + off) = __bfloat16_as_ushort(l);
}
// load a fp32 row of 64 (16 float4) and split-store into TMEM cols [0,32) hi/lo
__device__ __forceinline__ void stage_row64(const float4* src, uint32_t tm_hi, uint32_t tm_lo) {
    float4 v[16];
#pragma unroll
    for (int j = 0; j < 16; j++) v[j] = src[j];
    uint32_t hi[32], lo[32];
#pragma unroll
    for (int j = 0; j < 16; j++) {
        split2(v[j].x, v[j].y, hi[2 * j], lo[2 * j]);
        split2(v[j].z, v[j].w, hi[2 * j + 1], lo[2 * j + 1]);
    }
    TC_ST_X32(tm_hi, hi);
    TC_ST_X32(tm_lo, lo);
}
#endif  // TC_PATH

// ===================== small kernels =====================
__global__ void zero_agg_kernel() {
    int i = blockIdx.x * blockDim.x + threadIdx.x;
    float4* p = (float4*)g_agg;
    for (; i < NN * 16; i += gridDim.x * blockDim.x) p[i] = make_float4(0.f, 0.f, 0.f, 0.f);
}

// ===================== pre kernel: Xsr = [x@We1_s | x@We1_r + be1] =====================
#define P_TP 0
#define P_MB 16
#define P_B1 64
#define P_WSH 1024
#define P_WSL 9216
#define P_WRH 17408
#define P_WRL 25600
#define P_SZ  33792
#define P_AHI 0
#define P_ALO 32
#define P_D0  64
#define P_D1  128

__global__ __launch_bounds__(256, 2)
void pre_mma_kernel(const float* __restrict__ x,
                    const float* __restrict__ We1, const float* __restrict__ be1) {
    extern __shared__ char smc[];
    const int tid = threadIdx.x;
#if TC_PATH
    const uint32_t sb = smem_u32(smc);
    const int wid = tid >> 5, lane = tid & 31;
    if (wid == 0) { TC_ALLOC(sb + P_TP, 256); TC_RELINQ(); }
    if (tid == 0) MB_INIT(sb + P_MB, 1);
    float* b1s = (float*)(smc + P_B1);
    if (tid < 64) b1s[tid] = be1[tid];
    for (int i = tid; i < 4096; i += 256) {
        int k = i >> 6, n = i & 63;
        uint32_t o = OFFB(n, k);
        store_wsplit(smc, P_WSH, P_WSL, o, We1[(64 + k) * 64 + n]);
        store_wsplit(smc, P_WRH, P_WRL, o, We1[(128 + k) * 64 + n]);
    }
    __syncthreads();
    uint32_t tmem;
    asm volatile("ld.shared.b32 %0, [%1];" : "=r"(tmem) : "r"(sb + P_TP));
    const u64 dWsh = mkdesc(sb + P_WSH), dWsl = mkdesc(sb + P_WSL);
    const u64 dWrh = mkdesc(sb + P_WRH), dWrl = mkdesc(sb + P_WRL);
    uint32_t ph = 0;
    const int blk = wid & 3;
    const uint32_t rowoff = (uint32_t)blk << 21;
    const int row = blk * 32 + lane;
    const int c0 = (wid >= 4) ? 32 : 0;
    uint32_t d[32];
    const int NT = (NN + 127) / 128;
    const float4* x4 = (const float4*)x;
    float4 zero4 = make_float4(0.f, 0.f, 0.f, 0.f);

    for (int tile = blockIdx.x; tile < NT; tile += gridDim.x) {
        const int base = tile * 128;
        const int n = base + row;
        {
            float4 v[16];
            if (n < NN) {
#pragma unroll
                for (int j = 0; j < 16; j++) v[j] = x4[(size_t)n * 16 + j];
            } else {
#pragma unroll
                for (int j = 0; j < 16; j++) v[j] = zero4;
            }
            uint32_t hi[32], lo[32];
#pragma unroll
            for (int j = 0; j < 16; j++) {
                split2(v[j].x, v[j].y, hi[2 * j], lo[2 * j]);
                split2(v[j].z, v[j].w, hi[2 * j + 1], lo[2 * j + 1]);
            }
            if (wid < 4) TC_ST_X32(tmem + P_AHI + rowoff, hi);
            else         TC_ST_X32(tmem + P_ALO + rowoff, lo);
        }
        TC_WST(); TC_FB();
        __syncthreads();
        if (wid == 0 && elect1()) {
            TC_FA();
            mma_layer_ts(tmem + P_D0, tmem + P_AHI, tmem + P_ALO, dWsh, dWsl, 4, 0u);
            mma_layer_ts(tmem + P_D1, tmem + P_AHI, tmem + P_ALO, dWrh, dWrl, 4, 0u);
            TC_COMMIT(sb + P_MB);
        }
        MB_WAIT(sb + P_MB, ph); ph ^= 1;
        TC_FA();
        if (n < NN) {
            TC_LD_X32(d, tmem + P_D0 + c0);
            TC_WLD();
#pragma unroll
            for (int j = 0; j < 8; j++)
                *(float4*)&g_Xsr[(size_t)n * 128 + c0 + 4 * j] =
                    make_float4(__uint_as_float(d[4 * j]), __uint_as_float(d[4 * j + 1]),
                                __uint_as_float(d[4 * j + 2]), __uint_as_float(d[4 * j + 3]));
            TC_LD_X32(d, tmem + P_D1 + c0);
            TC_WLD();
#pragma unroll
            for (int j = 0; j < 8; j++)
                *(float4*)&g_Xsr[(size_t)n * 128 + 64 + c0 + 4 * j] =
                    make_float4(__uint_as_float(d[4 * j]) + b1s[c0 + 4 * j],
                                __uint_as_float(d[4 * j + 1]) + b1s[c0 + 4 * j + 1],
                                __uint_as_float(d[4 * j + 2]) + b1s[c0 + 4 * j + 2],
                                __uint_as_float(d[4 * j + 3]) + b1s[c0 + 4 * j + 3]);
        } else {
            TC_LD_X32(d, tmem + P_D0 + c0); TC_WLD();
            TC_LD_X32(d, tmem + P_D1 + c0); TC_WLD();
        }
        TC_FB();
        __syncthreads();
    }
    if (wid == 0) TC_DEALLOC(tmem, 256);
#else
    for (int i = blockIdx.x * blockDim.x + tid; i < NN; i += gridDim.x * blockDim.x)
        for (int j = 0; j < 64; j++) {
            float s = 0.f, r = be1[j];
            for (int k = 0; k < 64; k++) {
                s += x[(size_t)i * 64 + k] * We1[(64 + k) * 64 + j];
                r += x[(size_t)i * 64 + k] * We1[(128 + k) * 64 + j];
            }
            g_Xsr[(size_t)i * 128 + j] = s;
            g_Xsr[(size_t)i * 128 + 64 + j] = r;
        }
#endif
}

// ===================== edge kernel: half-granularity layer pipelining =====================
#define E_TP  0
#define E_MB0 16
#define E_MB1 24
#define E_B2  64
#define E_B3  320
#define E_W1H 1024
#define E_W1L 9216
#define E_W2H 17408
#define E_W2L 25600
#define E_W3H 33792
#define E_W3L 41984
#define E_SZ  50176
// TMEM (256 cols/CTA): h0: AHI 0 ALO 32 D 64; h1: AHI 128 ALO 160 D 192
#define H_AHI(h) ((h) ? 128u : 0u)
#define H_ALO(h) ((h) ? 160u : 32u)
#define H_D(h)   ((h) ? 192u : 64u)

__global__ __launch_bounds__(256, 2)
void edge_mma_kernel(const float* __restrict__ x,
                     const float* __restrict__ e,
                     const int* __restrict__ senders,
                     const int* __restrict__ receivers,
                     const float* __restrict__ We1, const float* __restrict__ be1,
                     const float* __restrict__ We2, const float* __restrict__ be2,
                     const float* __restrict__ We3, const float* __restrict__ be3) {
    extern __shared__ char smc[];
    const int tid = threadIdx.x;
#if TC_PATH
    const uint32_t sb = smem_u32(smc);
    const int wid = tid >> 5, lane = tid & 31;
    if (wid == 0) { TC_ALLOC(sb + E_TP, 256); TC_RELINQ(); }
    if (tid == 0) { MB_INIT(sb + E_MB0, 1); MB_INIT(sb + E_MB1, 1); }
    float* b2s = (float*)(smc + E_B2);
    float* b3s = (float*)(smc + E_B3);
    if (tid < 64) { b2s[tid] = be2[tid]; b3s[tid] = be3[tid]; }
    for (int i = tid; i < 4096; i += 256) {
        int k = i >> 6, n = i & 63;
        uint32_t o = OFFB(n, k);
        store_wsplit(smc, E_W1H, E_W1L, o, We1[k * 64 + n]);   // e-part rows [0,64)
        store_wsplit(smc, E_W2H, E_W2L, o, We2[i]);
        store_wsplit(smc, E_W3H, E_W3L, o, We3[i]);
    }
    __syncthreads();
    uint32_t tmem;
    asm volatile("ld.shared.b32 %0, [%1];" : "=r"(tmem) : "r"(sb + E_TP));
    const u64 dW1h = mkdesc(sb + E_W1H), dW1l = mkdesc(sb + E_W1L);
    const u64 dW2h = mkdesc(sb + E_W2H), dW2l = mkdesc(sb + E_W2L);
    const u64 dW3h = mkdesc(sb + E_W3H), dW3l = mkdesc(sb + E_W3L);
    const float4* e4 = (const float4*)e;
    uint32_t ph0 = 0, ph1 = 0;
    const int blk = wid & 3;
    const uint32_t rowoff = (uint32_t)blk << 21;
    const int row = blk * 32 + lane;
    const int half = (wid >= 4) ? 1 : 0;
    const int c0 = half ? 32 : 0;
    uint32_t d[32];
    const int NT2 = NE / 256;

    for (int tile = blockIdx.x; tile < NT2; tile += gridDim.x) {
        const int base = tile * 256;
        const int s0 = senders[base + row],        t0 = receivers[base + row];
        const int s1 = senders[base + 128 + row],  t1 = receivers[base + 128 + row];
        // ---- stage e rows of this warp's half ----
        stage_row64(&e4[(size_t)(base + half * 128 + row) * 16],
                    tmem + H_AHI(half) + rowoff, tmem + H_ALO(half) + rowoff);
        TC_WST(); TC_FB();
        __syncthreads();
        // ---- M1 h0 and h1 ----
        if (wid == 0 && elect1()) {
            TC_FA();
            mma_layer_ts(tmem + H_D(0), tmem + H_AHI(0), tmem + H_ALO(0), dW1h, dW1l, 4, 0u);
            TC_COMMIT(sb + E_MB0);
            mma_layer_ts(tmem + H_D(1), tmem + H_AHI(1), tmem + H_ALO(1), dW1h, dW1l, 4, 0u);
            TC_COMMIT(sb + E_MB1);
        }
        // ---- epi1 h0 ----
        MB_WAIT(sb + E_MB0, ph0); ph0 ^= 1;
        TC_FA();
        {
            TC_LD_X32(d, tmem + H_D(0) + c0);
            const float4* ps = (const float4*)&g_Xsr[(size_t)s0 * 128 + c0];
            const float4* pt = (const float4*)&g_Xsr[(size_t)t0 * 128 + 64 + c0];
            TC_WLD();
            uint32_t hi[16], lo[16];
#pragma unroll
            for (int j = 0; j < 8; j++) {
                float4 a = ps[j], b = pt[j];
                float v0 = fmaxf(__uint_as_float(d[4 * j])     + a.x + b.x, 0.f);
                float v1 = fmaxf(__uint_as_float(d[4 * j + 1]) + a.y + b.y, 0.f);
                float v2 = fmaxf(__uint_as_float(d[4 * j + 2]) + a.z + b.z, 0.f);
                float v3 = fmaxf(__uint_as_float(d[4 * j + 3]) + a.w + b.w, 0.f);
                split2(v0, v1, hi[2 * j], lo[2 * j]);
                split2(v2, v3, hi[2 * j + 1], lo[2 * j + 1]);
            }
            TC_ST_X16(tmem + H_AHI(0) + (c0 >> 1) + rowoff, hi);
            TC_ST_X16(tmem + H_ALO(0) + (c0 >> 1) + rowoff, lo);
        }
        TC_WST(); TC_FB();
        __syncthreads();
        // ---- M2 h0 issued now: runs while we do epi1 h1 ----
        if (wid == 0 && elect1()) {
            TC_FA();
            mma_layer_ts(tmem + H_D(0), tmem + H_AHI(0), tmem + H_ALO(0), dW2h, dW2l, 4, 0u);
            TC_COMMIT(sb + E_MB0);
        }
        // ---- epi1 h1 ----
        MB_WAIT(sb + E_MB1, ph1); ph1 ^= 1;
        TC_FA();
        {
            TC_LD_X32(d, tmem + H_D(1) + c0);
            const float4* ps = (const float4*)&g_Xsr[(size_t)s1 * 128 + c0];
            const float4* pt = (const float4*)&g_Xsr[(size_t)t1 * 128 + 64 + c0];
            TC_WLD();
            uint32_t hi[16], lo[16];
#pragma unroll
            for (int j = 0; j < 8; j++) {
                float4 a = ps[j], b = pt[j];
                float v0 = fmaxf(__uint_as_float(d[4 * j])     + a.x + b.x, 0.f);
                float v1 = fmaxf(__uint_as_float(d[4 * j + 1]) + a.y + b.y, 0.f);
                float v2 = fmaxf(__uint_as_float(d[4 * j + 2]) + a.z + b.z, 0.f);
                float v3 = fmaxf(__uint_as_float(d[4 * j + 3]) + a.w + b.w, 0.f);
                split2(v0, v1, hi[2 * j], lo[2 * j]);
                split2(v2, v3, hi[2 * j + 1], lo[2 * j + 1]);
            }
            TC_ST_X16(tmem + H_AHI(1) + (c0 >> 1) + rowoff, hi);
            TC_ST_X16(tmem + H_ALO(1) + (c0 >> 1) + rowoff, lo);
        }
        TC_WST(); TC_FB();
        __syncthreads();
        // ---- M2 h1 issued; runs while we do epi2 h0 ----
        if (wid == 0 && elect1()) {
            TC_FA();
            mma_layer_ts(tmem + H_D(1), tmem + H_AHI(1), tmem + H_ALO(1), dW2h, dW2l, 4, 0u);
            TC_COMMIT(sb + E_MB1);
        }
        // ---- epi2 h0 ----
        MB_WAIT(sb + E_MB0, ph0); ph0 ^= 1;
        TC_FA();
        {
            TC_LD_X32(d, tmem + H_D(0) + c0);
            TC_WLD();
            uint32_t hi[16], lo[16];
#pragma unroll
            for (int j = 0; j < 16; j++) {
                float a = fmaxf(__uint_as_float(d[2 * j])     + b2s[c0 + 2 * j], 0.f);
                float b = fmaxf(__uint_as_float(d[2 * j + 1]) + b2s[c0 + 2 * j + 1], 0.f);
                split2(a, b, hi[j], lo[j]);
            }
            TC_ST_X16(tmem + H_AHI(0) + (c0 >> 1) + rowoff, hi);
            TC_ST_X16(tmem + H_ALO(0) + (c0 >> 1) + rowoff, lo);
        }
        TC_WST(); TC_FB();
        __syncthreads();
        // ---- M3 h0 issued; runs while we do epi2 h1 ----
        if (wid == 0 && elect1()) {
            TC_FA();
            mma_layer_ts(tmem + H_D(0), tmem + H_AHI(0), tmem + H_ALO(0), dW3h, dW3l, 4, 0u);
            TC_COMMIT(sb + E_MB0);
        }
        // ---- epi2 h1 ----
        MB_WAIT(sb + E_MB1, ph1); ph1 ^= 1;
        TC_FA();
        {
            TC_LD_X32(d, tmem + H_D(1) + c0);
            TC_WLD();
            uint32_t hi[16], lo[16];
#pragma unroll
            for (int j = 0; j < 16; j++) {
                float a = fmaxf(__uint_as_float(d[2 * j])     + b2s[c0 + 2 * j], 0.f);
                float b = fmaxf(__uint_as_float(d[2 * j + 1]) + b2s[c0 + 2 * j + 1], 0.f);
                split2(a, b, hi[j], lo[j]);
            }
            TC_ST_X16(tmem + H_AHI(1) + (c0 >> 1) + rowoff, hi);
            TC_ST_X16(tmem + H_ALO(1) + (c0 >> 1) + rowoff, lo);
        }
        TC_WST(); TC_FB();
        __syncthreads();
        // ---- M3 h1 issued; runs while we do epi3 h0 ----
        if (wid == 0 && elect1()) {
            TC_FA();
            mma_layer_ts(tmem + H_D(1), tmem + H_AHI(1), tmem + H_ALO(1), dW3h, dW3l, 4, 0u);
            TC_COMMIT(sb + E_MB1);
        }
        // ---- epi3 h0: segment sum ----
        MB_WAIT(sb + E_MB0, ph0); ph0 ^= 1;
        TC_FA();
        {
            TC_LD_X32(d, tmem + H_D(0) + c0);
            TC_WLD();
            float* p = &g_agg[(size_t)t0 * 64 + c0];
#pragma unroll
            for (int jj = 0; jj < 4; jj++) {
                float v[8];
#pragma unroll
                for (int j = 0; j < 8; j++)
                    v[j] = __uint_as_float(d[jj * 8 + j]) + b3s[c0 + jj * 8 + j];
                red_add_v4(p + jj * 8, v[0], v[1], v[2], v[3]);
                red_add_v4(p + jj * 8 + 4, v[4], v[5], v[6], v[7]);
            }
        }
        // ---- epi3 h1: segment sum ----
        MB_WAIT(sb + E_MB1, ph1); ph1 ^= 1;
        TC_FA();
        {
            TC_LD_X32(d, tmem + H_D(1) + c0);
            TC_WLD();
            float* p = &g_agg[(size_t)t1 * 64 + c0];
#pragma unroll
            for (int jj = 0; jj < 4; jj++) {
                float v[8];
#pragma unroll
                for (int j = 0; j < 8; j++)
                    v[j] = __uint_as_float(d[jj * 8 + j]) + b3s[c0 + jj * 8 + j];
                red_add_v4(p + jj * 8, v[0], v[1], v[2], v[3]);
                red_add_v4(p + jj * 8 + 4, v[4], v[5], v[6], v[7]);
            }
        }
        TC_FB();
    }
    if (wid == 0) TC_DEALLOC(tmem, 256);
#else
    // naive correct fallback (compiled for non-sm_103a passes only)
    for (int i = blockIdx.x * blockDim.x + tid; i < NE; i += gridDim.x * blockDim.x) {
        int s = senders[i], t = receivers[i];
        float h1[64], h2[64];
        for (int j = 0; j < 64; j++) {
            float a = be1[j];
            for (int k = 0; k < 64; k++) a += e[(size_t)i * 64 + k] * We1[k * 64 + j];
            for (int k = 0; k < 64; k++) a += x[(size_t)s * 64 + k] * We1[(64 + k) * 64 + j];
            for (int k = 0; k < 64; k++) a += x[(size_t)t * 64 + k] * We1[(128 + k) * 64 + j];
            h1[j] = fmaxf(a, 0.f);
        }
        for (int j = 0; j < 64; j++) {
            float a = be2[j];
            for (int k = 0; k < 64; k++) a += h1[k] * We2[k * 64 + j];
            h2[j] = fmaxf(a, 0.f);
        }
        for (int j = 0; j < 64; j++) {
            float a = be3[j];
            for (int k = 0; k < 64; k++) a += h2[k] * We3[k * 64 + j];
            atomicAdd(&g_agg[(size_t)t * 64 + j], a);
        }
    }
#endif
}

// ===================== node kernel =====================
#define N_TP 0
#define N_MB 16
#define N_B1 64
#define N_B2 320
#define N_B3 576
#define N_W1H 1024
#define N_W1L 17408
#define N_W2H 33792
#define N_W2L 41984
#define N_W3H 50176
#define N_W3L 58368
#define N_SZ 66560
#define N_AHI 0
#define N_ALO 64
#define N_D   128

__global__ __launch_bounds__(256, 2)
void node_mma_kernel(const float* __restrict__ x,
                     const float* __restrict__ Wn1, const float* __restrict__ bn1,
                     const float* __restrict__ Wn2, const float* __restrict__ bn2,
                     const float* __restrict__ Wn3, const float* __restrict__ bn3,
                     float* __restrict__ out) {
    extern __shared__ char smc[];
    const int tid = threadIdx.x;
#if TC_PATH
    const uint32_t sb = smem_u32(smc);
    const int wid = tid >> 5, lane = tid & 31;
    if (wid == 0) { TC_ALLOC(sb + N_TP, 256); TC_RELINQ(); }
    if (tid == 0) MB_INIT(sb + N_MB, 1);
    float* b1s = (float*)(smc + N_B1);
    float* b2s = (float*)(smc + N_B2);
    float* b3s = (float*)(smc + N_B3);
    if (tid < 64) { b1s[tid] = bn1[tid]; b2s[tid] = bn2[tid]; b3s[tid] = bn3[tid]; }
    for (int i = tid; i < 8192; i += 256) {
        int k = i >> 6, n = i & 63;
        store_wsplit(smc, N_W1H, N_W1L, OFFB(n, k), Wn1[i]);
    }
    for (int i = tid; i < 4096; i += 256) {
        int k = i >> 6, n = i & 63;
        uint32_t o = OFFB(n, k);
        store_wsplit(smc, N_W2H, N_W2L, o, Wn2[i]);
        store_wsplit(smc, N_W3H, N_W3L, o, Wn3[i]);
    }
    __syncthreads();
    uint32_t tmem;
    asm volatile("ld.shared.b32 %0, [%1];" : "=r"(tmem) : "r"(sb + N_TP));
    const u64 dW1h = mkdesc(sb + N_W1H), dW1l = mkdesc(sb + N_W1L);
    const u64 dW2h = mkdesc(sb + N_W2H), dW2l = mkdesc(sb + N_W2L);
    const u64 dW3h = mkdesc(sb + N_W3H), dW3l = mkdesc(sb + N_W3L);
    const float4* x4 = (const float4*)x;
    const float4* ag4 = (const float4*)g_agg;
    uint32_t ph = 0;
    const int blk = wid & 3;
    const uint32_t rowoff = (uint32_t)blk << 21;
    const int row = blk * 32 + lane;
    const int c0 = (wid >= 4) ? 32 : 0;
    uint32_t d[32];
    const int NT = (NN + 127) / 128;
    float4 zero4 = make_float4(0.f, 0.f, 0.f, 0.f);

    for (int tile = blockIdx.x; tile < NT; tile += gridDim.x) {
        const int base = tile * 128;
        const int n = base + row;
        {
            const float4* src = (wid < 4) ? &x4[(size_t)n * 16] : &ag4[(size_t)n * 16];
            float4 v[16];
            if (n < NN) {
#pragma unroll
                for (int j = 0; j < 16; j++) v[j] = src[j];
            } else {
#pragma unroll
                for (int j = 0; j < 16; j++) v[j] = zero4;
            }
            uint32_t hi[32], lo[32];
#pragma unroll
            for (int j = 0; j < 16; j++) {
                split2(v[j].x, v[j].y, hi[2 * j], lo[2 * j]);
                split2(v[j].z, v[j].w, hi[2 * j + 1], lo[2 * j + 1]);
            }
            uint32_t off = (wid < 4) ? 0u : 32u;
            TC_ST_X32(tmem + N_AHI + off + rowoff, hi);
            TC_ST_X32(tmem + N_ALO + off + rowoff, lo);
        }
        TC_WST(); TC_FB();
        __syncthreads();
        if (wid == 0 && elect1()) {
            TC_FA();
            mma_layer_ts(tmem + N_D, tmem + N_AHI, tmem + N_ALO, dW1h, dW1l, 8, 0u);
            TC_COMMIT(sb + N_MB);
        }
        MB_WAIT(sb + N_MB, ph); ph ^= 1;
        TC_FA();
        TC_LD_X32(d, tmem + N_D + c0);
        TC_WLD();
        {
            uint32_t hi[16], lo[16];
#pragma unroll
            for (int j = 0; j < 16; j++) {
                float a = fmaxf(__uint_as_float(d[2 * j])     + b1s[c0 + 2 * j], 0.f);
                float b = fmaxf(__uint_as_float(d[2 * j + 1]) + b1s[c0 + 2 * j + 1], 0.f);
                split2(a, b, hi[j], lo[j]);
            }
            TC_ST_X16(tmem + N_AHI + (c0 >> 1) + rowoff, hi);
            TC_ST_X16(tmem + N_ALO + (c0 >> 1) + rowoff, lo);
            TC_WST();
        }
        TC_FB();
        __syncthreads();
        if (wid == 0 && elect1()) {
            TC_FA();
            mma_layer_ts(tmem + N_D, tmem + N_AHI, tmem + N_ALO, dW2h, dW2l, 4, 0u);
            TC_COMMIT(sb + N_MB);
        }
        MB_WAIT(sb + N_MB, ph); ph ^= 1;
        TC_FA();
        TC_LD_X32(d, tmem + N_D + c0);
        TC_WLD();
        {
            uint32_t hi[16], lo[16];
#pragma unroll
            for (int j = 0; j < 16; j++) {
                float a = fmaxf(__uint_as_float(d[2 * j])     + b2s[c0 + 2 * j], 0.f);
                float b = fmaxf(__uint_as_float(d[2 * j + 1]) + b2s[c0 + 2 * j + 1], 0.f);
                split2(a, b, hi[j], lo[j]);
            }
            TC_ST_X16(tmem + N_AHI + (c0 >> 1) + rowoff, hi);
            TC_ST_X16(tmem + N_ALO + (c0 >> 1) + rowoff, lo);
            TC_WST();
        }
        TC_FB();
        __syncthreads();
        if (wid == 0 && elect1()) {
            TC_FA();
            mma_layer_ts(tmem + N_D, tmem + N_AHI, tmem + N_ALO, dW3h, dW3l, 4, 0u);
            TC_COMMIT(sb + N_MB);
        }
        MB_WAIT(sb + N_MB, ph); ph ^= 1;
        TC_FA();
        TC_LD_X32(d, tmem + N_D + c0);
        TC_WLD(); TC_FB();
        if (n < NN) {
#pragma unroll
            for (int jj = 0; jj < 4; jj++) {
                float v[8];
#pragma unroll
                for (int j = 0; j < 8; j++)
                    v[j] = __uint_as_float(d[jj * 8 + j]) + b3s[c0 + jj * 8 + j];
                *(float4*)&out[(size_t)n * 64 + c0 + jj * 8]     = make_float4(v[0], v[1], v[2], v[3]);
                *(float4*)&out[(size_t)n * 64 + c0 + jj * 8 + 4] = make_float4(v[4], v[5], v[6], v[7]);
            }
        }
        __syncthreads();
    }
    if (wid == 0) TC_DEALLOC(tmem, 256);
#else
    for (int i = blockIdx.x * blockDim.x + tid; i < NN; i += gridDim.x * blockDim.x) {
        float h1[64], h2[64];
        for (int j = 0; j < 64; j++) {
            float a = bn1[j];
            for (int k = 0; k < 64; k++) a += x[(size_t)i * 64 + k] * Wn1[k * 64 + j];
            for (int k = 0; k < 64; k++) a += g_agg[(size_t)i * 64 + k] * Wn1[(64 + k) * 64 + j];
            h1[j] = fmaxf(a, 0.f);
        }
        for (int j = 0; j < 64; j++) {
            float a = bn2[j];
            for (int k = 0; k < 64; k++) a += h1[k] * Wn2[k * 64 + j];
            h2[j] = fmaxf(a, 0.f);
        }
        for (int j = 0; j < 64; j++) {
            float a = bn3[j];
            for (int k = 0; k < 64; k++) a += h2[k] * Wn3[k * 64 + j];
            out[(size_t)i * 64 + j] = a;
        }
    }
#endif
}

// ===================== launch =====================
extern "C" void kernel_launch(void* const* d_in, const int* in_sizes, int n_in,
                              void* d_out, int out_size) {
    const float* x         = (const float*)d_in[0];
    const float* e         = (const float*)d_in[1];
    const int*   senders   = (const int*)d_in[2];
    const int*   receivers = (const int*)d_in[3];
    const float* We1 = (const float*)d_in[4];
    const float* be1 = (const float*)d_in[5];
    const float* We2 = (const float*)d_in[6];
    const float* be2 = (const float*)d_in[7];
    const float* We3 = (const float*)d_in[8];
    const float* be3 = (const float*)d_in[9];
    const float* Wn1 = (const float*)d_in[10];
    const float* bn1 = (const float*)d_in[11];
    const float* Wn2 = (const float*)d_in[12];
    const float* bn2 = (const float*)d_in[13];
    const float* Wn3 = (const float*)d_in[14];
    const float* bn3 = (const float*)d_in[15];
    float* out = (float*)d_out;

    cudaFuncSetAttribute(pre_mma_kernel,  cudaFuncAttributeMaxDynamicSharedMemorySize, P_SZ);
    cudaFuncSetAttribute(edge_mma_kernel, cudaFuncAttributeMaxDynamicSharedMemorySize, E_SZ);
    cudaFuncSetAttribute(node_mma_kernel, cudaFuncAttributeMaxDynamicSharedMemorySize, N_SZ);

    zero_agg_kernel<<<304, 256>>>();
    pre_mma_kernel<<<304, 256, P_SZ>>>(x, We1, be1);
    edge_mma_kernel<<<304, 256, E_SZ>>>(x, e, senders, receivers,
                                        We1, be1, We2, be2, We3, be3);
    node_mma_kernel<<<304, 256, N_SZ>>>(x, Wn1, bn1, Wn2, bn2, Wn3, bn3, out);
}